// round 15
// baseline (speedup 1.0000x reference)
#include <cuda_runtime.h>
#include <cuda_fp16.h>
#include <cstdint>

#define NN 8192
#define EE 262144
#define DD 256
#define UMAX (EE + NN)
#define SLOT 128
#define BN_EPS 1e-5f

// GEMM tiling
#define BM 128
#define BNT 64
#define BK 32
#define ASH 40      // smem stride in halves
#define NSTAGE 3
#define NT (DD / BK)   // 8 K-tiles

// ---------------- device scratch ----------------
__device__ unsigned g_bitmap[NN * (NN / 32)];
__device__ int      g_deg[NN];
__device__ int      g_nz;
__device__ int      g_colidx[NN * SLOT];
__device__ float    g_dinv[NN];
__device__ __half   g_Xh[NN * DD];
__device__ __half   g_Wh[3][DD * DD];
__device__ __half   g_Ah[NN * DD];
__device__ __half   g_Zh[NN * DD];
__device__ float    g_Abuf[NN * DD];
__device__ float    g_sum[3][DD];
__device__ float    g_sumsq[3][DD];

// ---------------- preprocessing ----------------
__global__ void detect_k(const unsigned* __restrict__ e) {
    int i = blockIdx.x * blockDim.x + threadIdx.x;
    if (i < 4096 && e[2 * i + 1] != 0u) atomicOr(&g_nz, 1);
}

__global__ void dedup_k(const void* __restrict__ eptr) {
    int i = blockIdx.x * blockDim.x + threadIdx.x;
    if (i >= UMAX) return;
    int is64 = (g_nz == 0);
    int r, c;
    if (i < EE) {
        if (is64) {
            const long long* e = (const long long*)eptr;
            r = (int)e[i];
            c = (int)e[EE + i];
        } else {
            const int* e = (const int*)eptr;
            r = e[i];
            c = e[EE + i];
        }
    } else {
        r = c = i - EE;   // self loop
    }
    unsigned bit = (unsigned)r * NN + (unsigned)c;
    unsigned mask = 1u << (bit & 31u);
    unsigned old = atomicOr(&g_bitmap[bit >> 5], mask);
    if (!(old & mask)) {
        int slot = atomicAdd(&g_deg[r], 1);
        if (slot < SLOT) g_colidx[r * SLOT + slot] = c;
    }
}

__global__ void dinv_k() {
    int i = blockIdx.x * blockDim.x + threadIdx.x;
    if (i < NN) g_dinv[i] = rsqrtf((float)g_deg[i]);
}

// ---------------- fp32 -> fp16 elementwise (4 segments, 1 launch) ----------
__device__ __forceinline__ uint2 cvt4(float4 v) {
    __half2 lo = __floats2half2_rn(v.x, v.y);
    __half2 hi = __floats2half2_rn(v.z, v.w);
    uint2 u;
    u.x = *reinterpret_cast<unsigned*>(&lo);
    u.y = *reinterpret_cast<unsigned*>(&hi);
    return u;
}

#define N4X (NN * DD / 4)
#define N4W (DD * DD / 4)

__global__ void f2h4_k(const float4* __restrict__ x,  uint2* __restrict__ ox,
                       const float4* __restrict__ w1, const float4* __restrict__ w2,
                       const float4* __restrict__ w3, uint2* __restrict__ ow) {
    int i = blockIdx.x * blockDim.x + threadIdx.x;
    if (i < N4X) {
        ox[i] = cvt4(x[i]);
    } else {
        int j = i - N4X;
        if (j < N4W)            ow[j] = cvt4(w1[j]);
        else if (j < 2 * N4W)   ow[j] = cvt4(w2[j - N4W]);
        else if (j < 3 * N4W)   ow[j] = cvt4(w3[j - 2 * N4W]);
    }
}

// ---------------- BN + ReLU + cvt: Ah = fp16(relu(BN(Ab))) ----------------
__global__ __launch_bounds__(256) void bnrelu_k(const float* __restrict__ A,
                                                __half* __restrict__ Out, int layer,
                                                const float* __restrict__ gamma,
                                                const float* __restrict__ beta) {
    __shared__ float ssc[DD], ssh[DD];
    int tid = threadIdx.x;
    {
        float mu = g_sum[layer][tid] * (1.f / NN);
        float var = g_sumsq[layer][tid] * (1.f / NN) - mu * mu;
        float rs = rsqrtf(var + BN_EPS);
        float sc = gamma[tid] * rs;
        ssc[tid] = sc;
        ssh[tid] = beta[tid] - mu * sc;
    }
    __syncthreads();
    int i = blockIdx.x * 256 + tid;
    int col = (i * 4) & (DD - 1);
    float4 v = reinterpret_cast<const float4*>(A)[i];
    float a = fmaxf(fmaf(v.x, ssc[col],     ssh[col]),     0.f);
    float b = fmaxf(fmaf(v.y, ssc[col + 1], ssh[col + 1]), 0.f);
    float c = fmaxf(fmaf(v.z, ssc[col + 2], ssh[col + 2]), 0.f);
    float d = fmaxf(fmaf(v.w, ssc[col + 3], ssh[col + 3]), 0.f);
    __half2 lo = __floats2half2_rn(a, b);
    __half2 hi = __floats2half2_rn(c, d);
    uint2 u;
    u.x = *reinterpret_cast<unsigned*>(&lo);
    u.y = *reinterpret_cast<unsigned*>(&hi);
    reinterpret_cast<uint2*>(Out)[i] = u;
}

// ---------------- GEMM: Zh = A @ W^T + b  (fp16 HMMA, 3-stage cp.async) ------
__device__ __forceinline__ void cpa16(void* dst, const void* src) {
    unsigned d = (unsigned)__cvta_generic_to_shared(dst);
    asm volatile("cp.async.ca.shared.global [%0], [%1], 16;\n" :: "r"(d), "l"(src));
}

__global__ __launch_bounds__(256, 2) void gemm_k(
    const __half* __restrict__ Ain, const __half* __restrict__ W,
    const float* __restrict__ bias, __half* __restrict__ Z)
{
    extern __shared__ __half sm[];
    __half* As = sm;                          // [NSTAGE][BM][ASH]
    __half* Bs = sm + NSTAGE * BM * ASH;      // [NSTAGE][BNT][ASH]
#define AS(s,r,c) As[((s) * BM  + (r)) * ASH + (c)]
#define BS(s,r,c) Bs[((s) * BNT + (r)) * ASH + (c)]

    int tid = threadIdx.x;
    int bm = blockIdx.x * BM, bn = blockIdx.y * BNT;
    int wid = tid >> 5, lane = tid & 31;
    int g = lane >> 2, t = lane & 3;
    int wm = wid & 3, wn = wid >> 2;          // 4 x 2 warps, 32x32 per warp

    const __half* Abase = Ain + (size_t)bm * DD;
    const __half* Wbase = W + (size_t)bn * DD;

    int fa0_r = tid >> 2,          fa0_c = (tid & 3) * 8;
    int fa1_r = (tid + 256) >> 2,  fa1_c = (tid & 3) * 8;
    int fb_r  = tid >> 2,          fb_c  = (tid & 3) * 8;

    float acc[2][4][4];
    #pragma unroll
    for (int mt = 0; mt < 2; mt++)
        #pragma unroll
        for (int nt = 0; nt < 4; nt++)
            #pragma unroll
            for (int q = 0; q < 4; q++) acc[mt][nt][q] = 0.f;

    #pragma unroll
    for (int pk = 0; pk < 2; pk++) {
        int ko = pk * BK;
        cpa16(&AS(pk, fa0_r, fa0_c), Abase + fa0_r * DD + ko + fa0_c);
        cpa16(&AS(pk, fa1_r, fa1_c), Abase + fa1_r * DD + ko + fa1_c);
        cpa16(&BS(pk, fb_r, fb_c),  Wbase + fb_r * DD + ko + fb_c);
        asm volatile("cp.async.commit_group;");
    }

    #pragma unroll
    for (int kb = 0; kb < NT; kb++) {
        int s = kb % NSTAGE;
        if (kb + 2 < NT) {
            int sp = (kb + 2) % NSTAGE;
            int ko = (kb + 2) * BK;
            cpa16(&AS(sp, fa0_r, fa0_c), Abase + fa0_r * DD + ko + fa0_c);
            cpa16(&AS(sp, fa1_r, fa1_c), Abase + fa1_r * DD + ko + fa1_c);
            cpa16(&BS(sp, fb_r, fb_c),  Wbase + fb_r * DD + ko + fb_c);
            asm volatile("cp.async.commit_group;");
            asm volatile("cp.async.wait_group 2;");
        } else if (kb + 1 < NT) {
            asm volatile("cp.async.wait_group 1;");
        } else {
            asm volatile("cp.async.wait_group 0;");
        }
        __syncthreads();

        #pragma unroll
        for (int ks = 0; ks < 2; ks++) {
            int k16 = ks * 16;
            unsigned af[2][4], bf[4][2];
            #pragma unroll
            for (int mt = 0; mt < 2; mt++) {
                int rb = wm * 32 + mt * 16;
                af[mt][0] = *(const unsigned*)&AS(s, rb + g,     k16 + 2 * t);
                af[mt][1] = *(const unsigned*)&AS(s, rb + g + 8, k16 + 2 * t);
                af[mt][2] = *(const unsigned*)&AS(s, rb + g,     k16 + 2 * t + 8);
                af[mt][3] = *(const unsigned*)&AS(s, rb + g + 8, k16 + 2 * t + 8);
            }
            #pragma unroll
            for (int nt = 0; nt < 4; nt++) {
                int nb = wn * 32 + nt * 8;
                bf[nt][0] = *(const unsigned*)&BS(s, nb + g, k16 + 2 * t);
                bf[nt][1] = *(const unsigned*)&BS(s, nb + g, k16 + 2 * t + 8);
            }
            #pragma unroll
            for (int mt = 0; mt < 2; mt++)
                #pragma unroll
                for (int nt = 0; nt < 4; nt++) {
                    asm volatile(
                        "mma.sync.aligned.m16n8k16.row.col.f32.f16.f16.f32 "
                        "{%0,%1,%2,%3},{%4,%5,%6,%7},{%8,%9},{%0,%1,%2,%3};"
                        : "+f"(acc[mt][nt][0]), "+f"(acc[mt][nt][1]),
                          "+f"(acc[mt][nt][2]), "+f"(acc[mt][nt][3])
                        : "r"(af[mt][0]), "r"(af[mt][1]), "r"(af[mt][2]), "r"(af[mt][3]),
                          "r"(bf[nt][0]), "r"(bf[nt][1]));
                }
        }
        __syncthreads();
    }

    #pragma unroll
    for (int mt = 0; mt < 2; mt++)
        #pragma unroll
        for (int nt = 0; nt < 4; nt++) {
            int r0 = bm + wm * 32 + mt * 16 + g;
            int col = bn + wn * 32 + nt * 8 + 2 * t;
            float b0 = bias[col], b1 = bias[col + 1];
            __half2 p0 = __floats2half2_rn(acc[mt][nt][0] + b0, acc[mt][nt][1] + b1);
            __half2 p1 = __floats2half2_rn(acc[mt][nt][2] + b0, acc[mt][nt][3] + b1);
            *reinterpret_cast<__half2*>(Z + (size_t)r0 * DD + col)       = p0;
            *reinterpret_cast<__half2*>(Z + (size_t)(r0 + 8) * DD + col) = p1;
        }
#undef AS
#undef BS
}

// ---------------- sparse aggregation (fp16 Z) + fused BN stats ----------------
__global__ __launch_bounds__(256) void agg_k(const __half* __restrict__ Z,
                                             float* __restrict__ Out, int layer) {
    __shared__ float sv[8][DD];
    int tid = threadIdx.x;
    int w = tid >> 5;
    int row = blockIdx.x * 8 + w;
    int lane = tid & 31;

    int deg = g_deg[row];
    const int* cols = &g_colidx[row * SLOT];
    float a[8];
    #pragma unroll
    for (int j = 0; j < 8; j++) a[j] = 0.f;

    int p = 0;
    for (; p + 4 <= deg; p += 4) {
        int cc[4];
        #pragma unroll
        for (int q = 0; q < 4; q++) cc[q] = cols[p + q];
        float dv[4];
        uint4 u[4];
        #pragma unroll
        for (int q = 0; q < 4; q++) {
            dv[q] = g_dinv[cc[q]];
            u[q] = __ldg((const uint4*)(Z + (size_t)cc[q] * DD) + lane);
        }
        #pragma unroll
        for (int q = 0; q < 4; q++) {
            float2 f0 = __half22float2(*reinterpret_cast<__half2*>(&u[q].x));
            float2 f1 = __half22float2(*reinterpret_cast<__half2*>(&u[q].y));
            float2 f2 = __half22float2(*reinterpret_cast<__half2*>(&u[q].z));
            float2 f3 = __half22float2(*reinterpret_cast<__half2*>(&u[q].w));
            a[0] = fmaf(dv[q], f0.x, a[0]); a[1] = fmaf(dv[q], f0.y, a[1]);
            a[2] = fmaf(dv[q], f1.x, a[2]); a[3] = fmaf(dv[q], f1.y, a[3]);
            a[4] = fmaf(dv[q], f2.x, a[4]); a[5] = fmaf(dv[q], f2.y, a[5]);
            a[6] = fmaf(dv[q], f3.x, a[6]); a[7] = fmaf(dv[q], f3.y, a[7]);
        }
    }
    for (; p < deg; p++) {
        int c = cols[p];
        float dv = g_dinv[c];
        uint4 u = __ldg((const uint4*)(Z + (size_t)c * DD) + lane);
        float2 f0 = __half22float2(*reinterpret_cast<__half2*>(&u.x));
        float2 f1 = __half22float2(*reinterpret_cast<__half2*>(&u.y));
        float2 f2 = __half22float2(*reinterpret_cast<__half2*>(&u.z));
        float2 f3 = __half22float2(*reinterpret_cast<__half2*>(&u.w));
        a[0] = fmaf(dv, f0.x, a[0]); a[1] = fmaf(dv, f0.y, a[1]);
        a[2] = fmaf(dv, f1.x, a[2]); a[3] = fmaf(dv, f1.y, a[3]);
        a[4] = fmaf(dv, f2.x, a[4]); a[5] = fmaf(dv, f2.y, a[5]);
        a[6] = fmaf(dv, f3.x, a[6]); a[7] = fmaf(dv, f3.y, a[7]);
    }
    float dr = g_dinv[row];
    #pragma unroll
    for (int j = 0; j < 8; j++) a[j] *= dr;

    float4* orow = reinterpret_cast<float4*>(Out + (size_t)row * DD);
    orow[lane * 2]     = make_float4(a[0], a[1], a[2], a[3]);
    orow[lane * 2 + 1] = make_float4(a[4], a[5], a[6], a[7]);

    #pragma unroll
    for (int j = 0; j < 8; j++) sv[w][lane * 8 + j] = a[j];
    __syncthreads();
    float s = 0.f, ss = 0.f;
    #pragma unroll
    for (int r = 0; r < 8; r++) {
        float v = sv[r][tid];
        s += v;
        ss = fmaf(v, v, ss);
    }
    atomicAdd(&g_sum[layer][tid], s);
    atomicAdd(&g_sumsq[layer][tid], ss);
}

// final BN apply (fp32 out, no relu)
__global__ __launch_bounds__(256) void apply_k(const float* __restrict__ A,
                                               float* __restrict__ out,
                                               const float* __restrict__ gamma,
                                               const float* __restrict__ beta) {
    __shared__ float ssc[DD], ssh[DD];
    int tid = threadIdx.x;
    {
        float mu = g_sum[2][tid] * (1.f / NN);
        float var = g_sumsq[2][tid] * (1.f / NN) - mu * mu;
        float rs = rsqrtf(var + BN_EPS);
        float sc = gamma[tid] * rs;
        ssc[tid] = sc;
        ssh[tid] = beta[tid] - mu * sc;
    }
    __syncthreads();
    int i = blockIdx.x * 256 + tid;
    int col = (i * 4) & (DD - 1);
    float4 v = reinterpret_cast<const float4*>(A)[i];
    float4 o;
    o.x = fmaf(v.x, ssc[col],     ssh[col]);
    o.y = fmaf(v.y, ssc[col + 1], ssh[col + 1]);
    o.z = fmaf(v.z, ssc[col + 2], ssh[col + 2]);
    o.w = fmaf(v.w, ssc[col + 3], ssh[col + 3]);
    reinterpret_cast<float4*>(out)[i] = o;
}

// ---------------- launch ----------------
extern "C" void kernel_launch(void* const* d_in, const int* in_sizes, int n_in,
                              void* d_out, int out_size) {
    const float* x   = (const float*)d_in[0];
    const void*  ei  = d_in[1];
    const float* W1  = (const float*)d_in[2];
    const float* b1  = (const float*)d_in[3];
    const float* W2  = (const float*)d_in[4];
    const float* b2  = (const float*)d_in[5];
    const float* W3  = (const float*)d_in[6];
    const float* b3  = (const float*)d_in[7];
    const float* g1  = (const float*)d_in[8];
    const float* be1 = (const float*)d_in[9];
    const float* g2  = (const float*)d_in[10];
    const float* be2 = (const float*)d_in[11];
    const float* g3  = (const float*)d_in[12];
    const float* be3 = (const float*)d_in[13];
    float* out = (float*)d_out;

    void *pZ, *pA, *pBm, *pDeg, *pSum, *pSq, *pNz, *pXh, *pWh, *pAh;
    cudaGetSymbolAddress(&pZ, g_Zh);
    cudaGetSymbolAddress(&pA, g_Abuf);
    cudaGetSymbolAddress(&pBm, g_bitmap);
    cudaGetSymbolAddress(&pDeg, g_deg);
    cudaGetSymbolAddress(&pSum, g_sum);
    cudaGetSymbolAddress(&pSq, g_sumsq);
    cudaGetSymbolAddress(&pNz, g_nz);
    cudaGetSymbolAddress(&pXh, g_Xh);
    cudaGetSymbolAddress(&pWh, g_Wh);
    cudaGetSymbolAddress(&pAh, g_Ah);
    __half* Zh = (__half*)pZ;
    float*  Ab = (float*)pA;
    __half* Xh = (__half*)pXh;
    __half* Wh = (__half*)pWh;
    __half* Ah = (__half*)pAh;

    const int GEMM_SMEM = NSTAGE * (BM * ASH + BNT * ASH) * 2;   // bytes
    cudaFuncSetAttribute(gemm_k, cudaFuncAttributeMaxDynamicSharedMemorySize, GEMM_SMEM);

    static cudaStream_t s_pre = nullptr;
    static cudaEvent_t ev_fork = nullptr, ev_join = nullptr;
    if (s_pre == nullptr) {
        cudaStreamCreateWithFlags(&s_pre, cudaStreamNonBlocking);
        cudaEventCreateWithFlags(&ev_fork, cudaEventDisableTiming);
        cudaEventCreateWithFlags(&ev_join, cudaEventDisableTiming);
    }

    cudaMemsetAsync(pSum, 0, sizeof(float) * 3 * DD);
    cudaMemsetAsync(pSq, 0, sizeof(float) * 3 * DD);

    // main: all fp32->fp16 conversions in ONE launch (x, W1, W2, W3)
    f2h4_k<<<(N4X + 3 * N4W + 255) / 256, 256>>>(
        (const float4*)x, (uint2*)Xh,
        (const float4*)W1, (const float4*)W2, (const float4*)W3,
        (uint2*)Wh);

    // ---- fork: graph preprocessing only, concurrent with convert + gemm1
    cudaEventRecord(ev_fork, 0);
    cudaStreamWaitEvent(s_pre, ev_fork, 0);
    cudaMemsetAsync(pBm, 0, sizeof(unsigned) * NN * (NN / 32), s_pre);
    cudaMemsetAsync(pDeg, 0, sizeof(int) * NN, s_pre);
    cudaMemsetAsync(pNz, 0, sizeof(int), s_pre);
    detect_k<<<16, 256, 0, s_pre>>>((const unsigned*)ei);
    dedup_k<<<(UMAX + 255) / 256, 256, 0, s_pre>>>(ei);
    dinv_k<<<NN / 256, 256, 0, s_pre>>>();
    cudaEventRecord(ev_join, s_pre);

    dim3 ggrid(NN / BM, DD / BNT);

    // layer 1 — concurrent with preprocessing fork
    gemm_k<<<ggrid, 256, GEMM_SMEM>>>(Xh, Wh + 0 * DD * DD, b1, Zh);
    cudaStreamWaitEvent(0, ev_join, 0);   // agg needs CSR + dinv

    agg_k<<<NN / 8, 256>>>(Zh, Ab, 0);
    bnrelu_k<<<NN * DD / 4 / 256, 256>>>(Ab, Ah, 0, g1, be1);
    gemm_k<<<ggrid, 256, GEMM_SMEM>>>(Ah, Wh + 1 * DD * DD, b2, Zh);
    agg_k<<<NN / 8, 256>>>(Zh, Ab, 1);
    bnrelu_k<<<NN * DD / 4 / 256, 256>>>(Ab, Ah, 1, g2, be2);
    gemm_k<<<ggrid, 256, GEMM_SMEM>>>(Ah, Wh + 2 * DD * DD, b3, Zh);
    agg_k<<<NN / 8, 256>>>(Zh, Ab, 2);

    apply_k<<<NN * DD / 4 / 256, 256>>>(Ab, out, g3, be3);
}

// round 16
// speedup vs baseline: 1.0846x; 1.0846x over previous
#include <cuda_runtime.h>
#include <cuda_fp16.h>
#include <cstdint>

#define NN 8192
#define EE 262144
#define DD 256
#define UMAX (EE + NN)
#define SLOT 128
#define BN_EPS 1e-5f

// GEMM tiling
#define BM 128
#define BNT 64
#define BK 32
#define ASH 40      // smem stride in halves
#define NSTAGE 3
#define NT (DD / BK)   // 8 K-tiles

// ---------------- device scratch ----------------
__device__ unsigned g_bitmap[NN * (NN / 32)];
__device__ int      g_deg[NN];
__device__ int      g_colidx[NN * SLOT];
__device__ __half   g_Xh[NN * DD];
__device__ __half   g_Wh[3][DD * DD];
__device__ __half   g_Ah[NN * DD];
__device__ __half   g_Zh[NN * DD];
__device__ float    g_Abuf[NN * DD];
__device__ float    g_stats[2][3][DD];   // [0]=sum, [1]=sumsq

// ---------------- preprocessing ----------------
// Dedup via bitmap; self-detects int64 vs int32 edge dtype.
// int64 (values < 8192) => words 1,3,5,7 (odd halves of first 4 values) all 0.
// int32 => those are 4 independent random node ids; all-zero ~ 8192^-4.
__global__ void dedup_k(const void* __restrict__ eptr) {
    int i = blockIdx.x * blockDim.x + threadIdx.x;
    if (i >= UMAX) return;
    const unsigned* ew = (const unsigned*)eptr;
    int is64 = ((ew[1] | ew[3] | ew[5] | ew[7]) == 0u);
    int r, c;
    if (i < EE) {
        if (is64) {
            const long long* e = (const long long*)eptr;
            r = (int)e[i];
            c = (int)e[EE + i];
        } else {
            const int* e = (const int*)eptr;
            r = e[i];
            c = e[EE + i];
        }
    } else {
        r = c = i - EE;   // self loop
    }
    unsigned bit = (unsigned)r * NN + (unsigned)c;
    unsigned mask = 1u << (bit & 31u);
    unsigned old = atomicOr(&g_bitmap[bit >> 5], mask);
    if (!(old & mask)) {
        int slot = atomicAdd(&g_deg[r], 1);
        if (slot < SLOT) g_colidx[r * SLOT + slot] = c;
    }
}

// ---------------- fp32 -> fp16 elementwise (4 segments, 1 launch) ----------
__device__ __forceinline__ uint2 cvt4(float4 v) {
    __half2 lo = __floats2half2_rn(v.x, v.y);
    __half2 hi = __floats2half2_rn(v.z, v.w);
    uint2 u;
    u.x = *reinterpret_cast<unsigned*>(&lo);
    u.y = *reinterpret_cast<unsigned*>(&hi);
    return u;
}

#define N4X (NN * DD / 4)
#define N4W (DD * DD / 4)

__global__ void f2h4_k(const float4* __restrict__ x,  uint2* __restrict__ ox,
                       const float4* __restrict__ w1, const float4* __restrict__ w2,
                       const float4* __restrict__ w3, uint2* __restrict__ ow) {
    int i = blockIdx.x * blockDim.x + threadIdx.x;
    if (i < N4X) {
        ox[i] = cvt4(x[i]);
    } else {
        int j = i - N4X;
        if (j < N4W)            ow[j] = cvt4(w1[j]);
        else if (j < 2 * N4W)   ow[j] = cvt4(w2[j - N4W]);
        else if (j < 3 * N4W)   ow[j] = cvt4(w3[j - 2 * N4W]);
    }
}

// ---------------- BN + ReLU + cvt: Ah = fp16(relu(BN(Ab))) ----------------
__global__ __launch_bounds__(256) void bnrelu_k(const float* __restrict__ A,
                                                __half* __restrict__ Out, int layer,
                                                const float* __restrict__ gamma,
                                                const float* __restrict__ beta) {
    __shared__ float ssc[DD], ssh[DD];
    int tid = threadIdx.x;
    {
        float mu = g_stats[0][layer][tid] * (1.f / NN);
        float var = g_stats[1][layer][tid] * (1.f / NN) - mu * mu;
        float rs = rsqrtf(var + BN_EPS);
        float sc = gamma[tid] * rs;
        ssc[tid] = sc;
        ssh[tid] = beta[tid] - mu * sc;
    }
    __syncthreads();
    int i = blockIdx.x * 256 + tid;
    int col = (i * 4) & (DD - 1);
    float4 v = reinterpret_cast<const float4*>(A)[i];
    float a = fmaxf(fmaf(v.x, ssc[col],     ssh[col]),     0.f);
    float b = fmaxf(fmaf(v.y, ssc[col + 1], ssh[col + 1]), 0.f);
    float c = fmaxf(fmaf(v.z, ssc[col + 2], ssh[col + 2]), 0.f);
    float d = fmaxf(fmaf(v.w, ssc[col + 3], ssh[col + 3]), 0.f);
    __half2 lo = __floats2half2_rn(a, b);
    __half2 hi = __floats2half2_rn(c, d);
    uint2 u;
    u.x = *reinterpret_cast<unsigned*>(&lo);
    u.y = *reinterpret_cast<unsigned*>(&hi);
    reinterpret_cast<uint2*>(Out)[i] = u;
}

// ---------------- GEMM: Zh = A @ W^T + b  (fp16 HMMA, 3-stage cp.async) ------
__device__ __forceinline__ void cpa16(void* dst, const void* src) {
    unsigned d = (unsigned)__cvta_generic_to_shared(dst);
    asm volatile("cp.async.ca.shared.global [%0], [%1], 16;\n" :: "r"(d), "l"(src));
}

__global__ __launch_bounds__(256, 2) void gemm_k(
    const __half* __restrict__ Ain, const __half* __restrict__ W,
    const float* __restrict__ bias, __half* __restrict__ Z)
{
    extern __shared__ __half sm[];
    __half* As = sm;                          // [NSTAGE][BM][ASH]
    __half* Bs = sm + NSTAGE * BM * ASH;      // [NSTAGE][BNT][ASH]
#define AS(s,r,c) As[((s) * BM  + (r)) * ASH + (c)]
#define BS(s,r,c) Bs[((s) * BNT + (r)) * ASH + (c)]

    int tid = threadIdx.x;
    int bm = blockIdx.x * BM, bn = blockIdx.y * BNT;
    int wid = tid >> 5, lane = tid & 31;
    int g = lane >> 2, t = lane & 3;
    int wm = wid & 3, wn = wid >> 2;          // 4 x 2 warps, 32x32 per warp

    const __half* Abase = Ain + (size_t)bm * DD;
    const __half* Wbase = W + (size_t)bn * DD;

    int fa0_r = tid >> 2,          fa0_c = (tid & 3) * 8;
    int fa1_r = (tid + 256) >> 2,  fa1_c = (tid & 3) * 8;
    int fb_r  = tid >> 2,          fb_c  = (tid & 3) * 8;

    float acc[2][4][4];
    #pragma unroll
    for (int mt = 0; mt < 2; mt++)
        #pragma unroll
        for (int nt = 0; nt < 4; nt++)
            #pragma unroll
            for (int q = 0; q < 4; q++) acc[mt][nt][q] = 0.f;

    #pragma unroll
    for (int pk = 0; pk < 2; pk++) {
        int ko = pk * BK;
        cpa16(&AS(pk, fa0_r, fa0_c), Abase + fa0_r * DD + ko + fa0_c);
        cpa16(&AS(pk, fa1_r, fa1_c), Abase + fa1_r * DD + ko + fa1_c);
        cpa16(&BS(pk, fb_r, fb_c),  Wbase + fb_r * DD + ko + fb_c);
        asm volatile("cp.async.commit_group;");
    }

    #pragma unroll
    for (int kb = 0; kb < NT; kb++) {
        int s = kb % NSTAGE;
        if (kb + 2 < NT) {
            int sp = (kb + 2) % NSTAGE;
            int ko = (kb + 2) * BK;
            cpa16(&AS(sp, fa0_r, fa0_c), Abase + fa0_r * DD + ko + fa0_c);
            cpa16(&AS(sp, fa1_r, fa1_c), Abase + fa1_r * DD + ko + fa1_c);
            cpa16(&BS(sp, fb_r, fb_c),  Wbase + fb_r * DD + ko + fb_c);
            asm volatile("cp.async.commit_group;");
            asm volatile("cp.async.wait_group 2;");
        } else if (kb + 1 < NT) {
            asm volatile("cp.async.wait_group 1;");
        } else {
            asm volatile("cp.async.wait_group 0;");
        }
        __syncthreads();

        #pragma unroll
        for (int ks = 0; ks < 2; ks++) {
            int k16 = ks * 16;
            unsigned af[2][4], bf[4][2];
            #pragma unroll
            for (int mt = 0; mt < 2; mt++) {
                int rb = wm * 32 + mt * 16;
                af[mt][0] = *(const unsigned*)&AS(s, rb + g,     k16 + 2 * t);
                af[mt][1] = *(const unsigned*)&AS(s, rb + g + 8, k16 + 2 * t);
                af[mt][2] = *(const unsigned*)&AS(s, rb + g,     k16 + 2 * t + 8);
                af[mt][3] = *(const unsigned*)&AS(s, rb + g + 8, k16 + 2 * t + 8);
            }
            #pragma unroll
            for (int nt = 0; nt < 4; nt++) {
                int nb = wn * 32 + nt * 8;
                bf[nt][0] = *(const unsigned*)&BS(s, nb + g, k16 + 2 * t);
                bf[nt][1] = *(const unsigned*)&BS(s, nb + g, k16 + 2 * t + 8);
            }
            #pragma unroll
            for (int mt = 0; mt < 2; mt++)
                #pragma unroll
                for (int nt = 0; nt < 4; nt++) {
                    asm volatile(
                        "mma.sync.aligned.m16n8k16.row.col.f32.f16.f16.f32 "
                        "{%0,%1,%2,%3},{%4,%5,%6,%7},{%8,%9},{%0,%1,%2,%3};"
                        : "+f"(acc[mt][nt][0]), "+f"(acc[mt][nt][1]),
                          "+f"(acc[mt][nt][2]), "+f"(acc[mt][nt][3])
                        : "r"(af[mt][0]), "r"(af[mt][1]), "r"(af[mt][2]), "r"(af[mt][3]),
                          "r"(bf[nt][0]), "r"(bf[nt][1]));
                }
        }
        __syncthreads();
    }

    #pragma unroll
    for (int mt = 0; mt < 2; mt++)
        #pragma unroll
        for (int nt = 0; nt < 4; nt++) {
            int r0 = bm + wm * 32 + mt * 16 + g;
            int col = bn + wn * 32 + nt * 8 + 2 * t;
            float b0 = bias[col], b1 = bias[col + 1];
            __half2 p0 = __floats2half2_rn(acc[mt][nt][0] + b0, acc[mt][nt][1] + b1);
            __half2 p1 = __floats2half2_rn(acc[mt][nt][2] + b0, acc[mt][nt][3] + b1);
            *reinterpret_cast<__half2*>(Z + (size_t)r0 * DD + col)       = p0;
            *reinterpret_cast<__half2*>(Z + (size_t)(r0 + 8) * DD + col) = p1;
        }
#undef AS
#undef BS
}

// ---------------- sparse aggregation (fp16 Z) + fused BN stats ----------------
// dinv computed inline from g_deg (rsqrt hidden under gather latency).
__global__ __launch_bounds__(256) void agg_k(const __half* __restrict__ Z,
                                             float* __restrict__ Out, int layer) {
    __shared__ float sv[8][DD];
    int tid = threadIdx.x;
    int w = tid >> 5;
    int row = blockIdx.x * 8 + w;
    int lane = tid & 31;

    int deg = g_deg[row];
    const int* cols = &g_colidx[row * SLOT];
    float a[8];
    #pragma unroll
    for (int j = 0; j < 8; j++) a[j] = 0.f;

    int p = 0;
    for (; p + 4 <= deg; p += 4) {
        int cc[4];
        #pragma unroll
        for (int q = 0; q < 4; q++) cc[q] = cols[p + q];
        float dv[4];
        uint4 u[4];
        #pragma unroll
        for (int q = 0; q < 4; q++) {
            dv[q] = rsqrtf((float)g_deg[cc[q]]);
            u[q] = __ldg((const uint4*)(Z + (size_t)cc[q] * DD) + lane);
        }
        #pragma unroll
        for (int q = 0; q < 4; q++) {
            float2 f0 = __half22float2(*reinterpret_cast<__half2*>(&u[q].x));
            float2 f1 = __half22float2(*reinterpret_cast<__half2*>(&u[q].y));
            float2 f2 = __half22float2(*reinterpret_cast<__half2*>(&u[q].z));
            float2 f3 = __half22float2(*reinterpret_cast<__half2*>(&u[q].w));
            a[0] = fmaf(dv[q], f0.x, a[0]); a[1] = fmaf(dv[q], f0.y, a[1]);
            a[2] = fmaf(dv[q], f1.x, a[2]); a[3] = fmaf(dv[q], f1.y, a[3]);
            a[4] = fmaf(dv[q], f2.x, a[4]); a[5] = fmaf(dv[q], f2.y, a[5]);
            a[6] = fmaf(dv[q], f3.x, a[6]); a[7] = fmaf(dv[q], f3.y, a[7]);
        }
    }
    for (; p < deg; p++) {
        int c = cols[p];
        float dv = rsqrtf((float)g_deg[c]);
        uint4 u = __ldg((const uint4*)(Z + (size_t)c * DD) + lane);
        float2 f0 = __half22float2(*reinterpret_cast<__half2*>(&u.x));
        float2 f1 = __half22float2(*reinterpret_cast<__half2*>(&u.y));
        float2 f2 = __half22float2(*reinterpret_cast<__half2*>(&u.z));
        float2 f3 = __half22float2(*reinterpret_cast<__half2*>(&u.w));
        a[0] = fmaf(dv, f0.x, a[0]); a[1] = fmaf(dv, f0.y, a[1]);
        a[2] = fmaf(dv, f1.x, a[2]); a[3] = fmaf(dv, f1.y, a[3]);
        a[4] = fmaf(dv, f2.x, a[4]); a[5] = fmaf(dv, f2.y, a[5]);
        a[6] = fmaf(dv, f3.x, a[6]); a[7] = fmaf(dv, f3.y, a[7]);
    }
    float dr = rsqrtf((float)deg);
    #pragma unroll
    for (int j = 0; j < 8; j++) a[j] *= dr;

    float4* orow = reinterpret_cast<float4*>(Out + (size_t)row * DD);
    orow[lane * 2]     = make_float4(a[0], a[1], a[2], a[3]);
    orow[lane * 2 + 1] = make_float4(a[4], a[5], a[6], a[7]);

    #pragma unroll
    for (int j = 0; j < 8; j++) sv[w][lane * 8 + j] = a[j];
    __syncthreads();
    float s = 0.f, ss = 0.f;
    #pragma unroll
    for (int r = 0; r < 8; r++) {
        float v = sv[r][tid];
        s += v;
        ss = fmaf(v, v, ss);
    }
    atomicAdd(&g_stats[0][layer][tid], s);
    atomicAdd(&g_stats[1][layer][tid], ss);
}

// final BN apply (fp32 out, no relu)
__global__ __launch_bounds__(256) void apply_k(const float* __restrict__ A,
                                               float* __restrict__ out,
                                               const float* __restrict__ gamma,
                                               const float* __restrict__ beta) {
    __shared__ float ssc[DD], ssh[DD];
    int tid = threadIdx.x;
    {
        float mu = g_stats[0][2][tid] * (1.f / NN);
        float var = g_stats[1][2][tid] * (1.f / NN) - mu * mu;
        float rs = rsqrtf(var + BN_EPS);
        float sc = gamma[tid] * rs;
        ssc[tid] = sc;
        ssh[tid] = beta[tid] - mu * sc;
    }
    __syncthreads();
    int i = blockIdx.x * 256 + tid;
    int col = (i * 4) & (DD - 1);
    float4 v = reinterpret_cast<const float4*>(A)[i];
    float4 o;
    o.x = fmaf(v.x, ssc[col],     ssh[col]);
    o.y = fmaf(v.y, ssc[col + 1], ssh[col + 1]);
    o.z = fmaf(v.z, ssc[col + 2], ssh[col + 2]);
    o.w = fmaf(v.w, ssc[col + 3], ssh[col + 3]);
    reinterpret_cast<float4*>(out)[i] = o;
}

// ---------------- launch ----------------
extern "C" void kernel_launch(void* const* d_in, const int* in_sizes, int n_in,
                              void* d_out, int out_size) {
    const float* x   = (const float*)d_in[0];
    const void*  ei  = d_in[1];
    const float* W1  = (const float*)d_in[2];
    const float* b1  = (const float*)d_in[3];
    const float* W2  = (const float*)d_in[4];
    const float* b2  = (const float*)d_in[5];
    const float* W3  = (const float*)d_in[6];
    const float* b3  = (const float*)d_in[7];
    const float* g1  = (const float*)d_in[8];
    const float* be1 = (const float*)d_in[9];
    const float* g2  = (const float*)d_in[10];
    const float* be2 = (const float*)d_in[11];
    const float* g3  = (const float*)d_in[12];
    const float* be3 = (const float*)d_in[13];
    float* out = (float*)d_out;

    void *pZ, *pA, *pBm, *pDeg, *pSt, *pXh, *pWh, *pAh;
    cudaGetSymbolAddress(&pZ, g_Zh);
    cudaGetSymbolAddress(&pA, g_Abuf);
    cudaGetSymbolAddress(&pBm, g_bitmap);
    cudaGetSymbolAddress(&pDeg, g_deg);
    cudaGetSymbolAddress(&pSt, g_stats);
    cudaGetSymbolAddress(&pXh, g_Xh);
    cudaGetSymbolAddress(&pWh, g_Wh);
    cudaGetSymbolAddress(&pAh, g_Ah);
    __half* Zh = (__half*)pZ;
    float*  Ab = (float*)pA;
    __half* Xh = (__half*)pXh;
    __half* Wh = (__half*)pWh;
    __half* Ah = (__half*)pAh;

    const int GEMM_SMEM = NSTAGE * (BM * ASH + BNT * ASH) * 2;   // bytes
    cudaFuncSetAttribute(gemm_k, cudaFuncAttributeMaxDynamicSharedMemorySize, GEMM_SMEM);

    static cudaStream_t s_pre = nullptr;
    static cudaEvent_t ev_fork = nullptr, ev_join = nullptr;
    if (s_pre == nullptr) {
        cudaStreamCreateWithFlags(&s_pre, cudaStreamNonBlocking);
        cudaEventCreateWithFlags(&ev_fork, cudaEventDisableTiming);
        cudaEventCreateWithFlags(&ev_join, cudaEventDisableTiming);
    }

    // BN accumulators: one merged memset
    cudaMemsetAsync(pSt, 0, sizeof(float) * 2 * 3 * DD);

    // ---- fork: graph preprocessing only (memsets + dedup), concurrent with
    //      convert + gemm1 on the main stream
    cudaEventRecord(ev_fork, 0);
    cudaStreamWaitEvent(s_pre, ev_fork, 0);
    cudaMemsetAsync(pBm, 0, sizeof(unsigned) * NN * (NN / 32), s_pre);
    cudaMemsetAsync(pDeg, 0, sizeof(int) * NN, s_pre);
    dedup_k<<<(UMAX + 255) / 256, 256, 0, s_pre>>>(ei);
    cudaEventRecord(ev_join, s_pre);

    // main: all fp32->fp16 conversions in ONE launch (x, W1, W2, W3)
    f2h4_k<<<(N4X + 3 * N4W + 255) / 256, 256>>>(
        (const float4*)x, (uint2*)Xh,
        (const float4*)W1, (const float4*)W2, (const float4*)W3,
        (uint2*)Wh);

    dim3 ggrid(NN / BM, DD / BNT);

    // layer 1 — concurrent with preprocessing fork
    gemm_k<<<ggrid, 256, GEMM_SMEM>>>(Xh, Wh + 0 * DD * DD, b1, Zh);
    cudaStreamWaitEvent(0, ev_join, 0);   // agg needs CSR + deg

    agg_k<<<NN / 8, 256>>>(Zh, Ab, 0);
    bnrelu_k<<<NN * DD / 4 / 256, 256>>>(Ab, Ah, 0, g1, be1);
    gemm_k<<<ggrid, 256, GEMM_SMEM>>>(Ah, Wh + 1 * DD * DD, b2, Zh);
    agg_k<<<NN / 8, 256>>>(Zh, Ab, 1);
    bnrelu_k<<<NN * DD / 4 / 256, 256>>>(Ab, Ah, 1, g2, be2);
    gemm_k<<<ggrid, 256, GEMM_SMEM>>>(Ah, Wh + 2 * DD * DD, b3, Zh);
    agg_k<<<NN / 8, 256>>>(Zh, Ab, 2);

    apply_k<<<NN * DD / 4 / 256, 256>>>(Ab, out, g3, be3);
}

// round 17
// speedup vs baseline: 1.1278x; 1.0399x over previous
#include <cuda_runtime.h>
#include <cuda_fp16.h>
#include <cstdint>

#define NN 8192
#define EE 262144
#define DD 256
#define UMAX (EE + NN)
#define SLOT 128
#define BN_EPS 1e-5f

// GEMM tiling
#define BM 128
#define BNT 64
#define BK 32
#define ASH 40      // smem stride in halves
#define NSTAGE 3
#define NT (DD / BK)   // 8 K-tiles

// ---------------- device scratch ----------------
__device__ unsigned g_bitmap[NN * (NN / 32)];
__device__ int      g_deg[NN];
__device__ int      g_colidx[NN * SLOT];
__device__ __half   g_Xh[NN * DD];
__device__ __half   g_Wh[3][DD * DD];
__device__ __half   g_Ah[NN * DD];
__device__ __half   g_Zh[NN * DD];
__device__ float    g_Abuf[NN * DD];
__device__ float    g_stats[2][3][DD];   // [0]=sum, [1]=sumsq

// ---------------- preprocessing ----------------
// Dedup via bitmap; self-detects int64 vs int32 edge dtype.
__global__ void dedup_k(const void* __restrict__ eptr) {
    int i = blockIdx.x * blockDim.x + threadIdx.x;
    if (i >= UMAX) return;
    const unsigned* ew = (const unsigned*)eptr;
    int is64 = ((ew[1] | ew[3] | ew[5] | ew[7]) == 0u);
    int r, c;
    if (i < EE) {
        if (is64) {
            const long long* e = (const long long*)eptr;
            r = (int)e[i];
            c = (int)e[EE + i];
        } else {
            const int* e = (const int*)eptr;
            r = e[i];
            c = e[EE + i];
        }
    } else {
        r = c = i - EE;   // self loop
    }
    unsigned bit = (unsigned)r * NN + (unsigned)c;
    unsigned mask = 1u << (bit & 31u);
    unsigned old = atomicOr(&g_bitmap[bit >> 5], mask);
    if (!(old & mask)) {
        int slot = atomicAdd(&g_deg[r], 1);
        if (slot < SLOT) g_colidx[r * SLOT + slot] = c;
    }
}

// ---------------- fp32 -> fp16 elementwise (4 segments, 1 launch) ----------
__device__ __forceinline__ uint2 cvt4(float4 v) {
    __half2 lo = __floats2half2_rn(v.x, v.y);
    __half2 hi = __floats2half2_rn(v.z, v.w);
    uint2 u;
    u.x = *reinterpret_cast<unsigned*>(&lo);
    u.y = *reinterpret_cast<unsigned*>(&hi);
    return u;
}

#define N4X (NN * DD / 4)
#define N4W (DD * DD / 4)

__global__ void f2h4_k(const float4* __restrict__ x,  uint2* __restrict__ ox,
                       const float4* __restrict__ w1, const float4* __restrict__ w2,
                       const float4* __restrict__ w3, uint2* __restrict__ ow) {
    int i = blockIdx.x * blockDim.x + threadIdx.x;
    if (i < N4X) {
        ox[i] = cvt4(x[i]);
    } else {
        int j = i - N4X;
        if (j < N4W)            ow[j] = cvt4(w1[j]);
        else if (j < 2 * N4W)   ow[j] = cvt4(w2[j - N4W]);
        else if (j < 3 * N4W)   ow[j] = cvt4(w3[j - 2 * N4W]);
    }
}

// ---------------- BN + ReLU + cvt: Ah = fp16(relu(BN(Ab))), ILP2 ----------
__global__ __launch_bounds__(256) void bnrelu_k(const float* __restrict__ A,
                                                __half* __restrict__ Out, int layer,
                                                const float* __restrict__ gamma,
                                                const float* __restrict__ beta) {
    __shared__ float ssc[DD], ssh[DD];
    int tid = threadIdx.x;
    {
        float mu = g_stats[0][layer][tid] * (1.f / NN);
        float var = g_stats[1][layer][tid] * (1.f / NN) - mu * mu;
        float rs = rsqrtf(var + BN_EPS);
        float sc = gamma[tid] * rs;
        ssc[tid] = sc;
        ssh[tid] = beta[tid] - mu * sc;
    }
    __syncthreads();
    const int H = NN * DD / 4 / 2;            // half range in float4 units
    int i = blockIdx.x * 256 + tid;
    #pragma unroll
    for (int half = 0; half < 2; half++) {
        int idx = i + half * H;
        int col = (idx * 4) & (DD - 1);
        float4 v = reinterpret_cast<const float4*>(A)[idx];
        float a = fmaxf(fmaf(v.x, ssc[col],     ssh[col]),     0.f);
        float b = fmaxf(fmaf(v.y, ssc[col + 1], ssh[col + 1]), 0.f);
        float c = fmaxf(fmaf(v.z, ssc[col + 2], ssh[col + 2]), 0.f);
        float d = fmaxf(fmaf(v.w, ssc[col + 3], ssh[col + 3]), 0.f);
        __half2 lo = __floats2half2_rn(a, b);
        __half2 hi = __floats2half2_rn(c, d);
        uint2 u;
        u.x = *reinterpret_cast<unsigned*>(&lo);
        u.y = *reinterpret_cast<unsigned*>(&hi);
        reinterpret_cast<uint2*>(Out)[idx] = u;
    }
}

// ---------------- GEMM: Zh = A @ W^T + b  (fp16 HMMA, 3-stage cp.async) ------
__device__ __forceinline__ void cpa16(void* dst, const void* src) {
    unsigned d = (unsigned)__cvta_generic_to_shared(dst);
    asm volatile("cp.async.ca.shared.global [%0], [%1], 16;\n" :: "r"(d), "l"(src));
}

__global__ __launch_bounds__(256, 2) void gemm_k(
    const __half* __restrict__ Ain, const __half* __restrict__ W,
    const float* __restrict__ bias, __half* __restrict__ Z)
{
    extern __shared__ __half sm[];
    __half* As = sm;                          // [NSTAGE][BM][ASH]
    __half* Bs = sm + NSTAGE * BM * ASH;      // [NSTAGE][BNT][ASH]
#define AS(s,r,c) As[((s) * BM  + (r)) * ASH + (c)]
#define BS(s,r,c) Bs[((s) * BNT + (r)) * ASH + (c)]

    int tid = threadIdx.x;
    int bm = blockIdx.x * BM, bn = blockIdx.y * BNT;
    int wid = tid >> 5, lane = tid & 31;
    int g = lane >> 2, t = lane & 3;
    int wm = wid & 3, wn = wid >> 2;          // 4 x 2 warps, 32x32 per warp

    const __half* Abase = Ain + (size_t)bm * DD;
    const __half* Wbase = W + (size_t)bn * DD;

    int fa0_r = tid >> 2,          fa0_c = (tid & 3) * 8;
    int fa1_r = (tid + 256) >> 2,  fa1_c = (tid & 3) * 8;
    int fb_r  = tid >> 2,          fb_c  = (tid & 3) * 8;

    float acc[2][4][4];
    #pragma unroll
    for (int mt = 0; mt < 2; mt++)
        #pragma unroll
        for (int nt = 0; nt < 4; nt++)
            #pragma unroll
            for (int q = 0; q < 4; q++) acc[mt][nt][q] = 0.f;

    #pragma unroll
    for (int pk = 0; pk < 2; pk++) {
        int ko = pk * BK;
        cpa16(&AS(pk, fa0_r, fa0_c), Abase + fa0_r * DD + ko + fa0_c);
        cpa16(&AS(pk, fa1_r, fa1_c), Abase + fa1_r * DD + ko + fa1_c);
        cpa16(&BS(pk, fb_r, fb_c),  Wbase + fb_r * DD + ko + fb_c);
        asm volatile("cp.async.commit_group;");
    }

    #pragma unroll
    for (int kb = 0; kb < NT; kb++) {
        int s = kb % NSTAGE;
        if (kb + 2 < NT) {
            int sp = (kb + 2) % NSTAGE;
            int ko = (kb + 2) * BK;
            cpa16(&AS(sp, fa0_r, fa0_c), Abase + fa0_r * DD + ko + fa0_c);
            cpa16(&AS(sp, fa1_r, fa1_c), Abase + fa1_r * DD + ko + fa1_c);
            cpa16(&BS(sp, fb_r, fb_c),  Wbase + fb_r * DD + ko + fb_c);
            asm volatile("cp.async.commit_group;");
            asm volatile("cp.async.wait_group 2;");
        } else if (kb + 1 < NT) {
            asm volatile("cp.async.wait_group 1;");
        } else {
            asm volatile("cp.async.wait_group 0;");
        }
        __syncthreads();

        #pragma unroll
        for (int ks = 0; ks < 2; ks++) {
            int k16 = ks * 16;
            unsigned af[2][4], bf[4][2];
            #pragma unroll
            for (int mt = 0; mt < 2; mt++) {
                int rb = wm * 32 + mt * 16;
                af[mt][0] = *(const unsigned*)&AS(s, rb + g,     k16 + 2 * t);
                af[mt][1] = *(const unsigned*)&AS(s, rb + g + 8, k16 + 2 * t);
                af[mt][2] = *(const unsigned*)&AS(s, rb + g,     k16 + 2 * t + 8);
                af[mt][3] = *(const unsigned*)&AS(s, rb + g + 8, k16 + 2 * t + 8);
            }
            #pragma unroll
            for (int nt = 0; nt < 4; nt++) {
                int nb = wn * 32 + nt * 8;
                bf[nt][0] = *(const unsigned*)&BS(s, nb + g, k16 + 2 * t);
                bf[nt][1] = *(const unsigned*)&BS(s, nb + g, k16 + 2 * t + 8);
            }
            #pragma unroll
            for (int mt = 0; mt < 2; mt++)
                #pragma unroll
                for (int nt = 0; nt < 4; nt++) {
                    asm volatile(
                        "mma.sync.aligned.m16n8k16.row.col.f32.f16.f16.f32 "
                        "{%0,%1,%2,%3},{%4,%5,%6,%7},{%8,%9},{%0,%1,%2,%3};"
                        : "+f"(acc[mt][nt][0]), "+f"(acc[mt][nt][1]),
                          "+f"(acc[mt][nt][2]), "+f"(acc[mt][nt][3])
                        : "r"(af[mt][0]), "r"(af[mt][1]), "r"(af[mt][2]), "r"(af[mt][3]),
                          "r"(bf[nt][0]), "r"(bf[nt][1]));
                }
        }
        __syncthreads();
    }

    #pragma unroll
    for (int mt = 0; mt < 2; mt++)
        #pragma unroll
        for (int nt = 0; nt < 4; nt++) {
            int r0 = bm + wm * 32 + mt * 16 + g;
            int col = bn + wn * 32 + nt * 8 + 2 * t;
            float b0 = bias[col], b1 = bias[col + 1];
            __half2 p0 = __floats2half2_rn(acc[mt][nt][0] + b0, acc[mt][nt][1] + b1);
            __half2 p1 = __floats2half2_rn(acc[mt][nt][2] + b0, acc[mt][nt][3] + b1);
            *reinterpret_cast<__half2*>(Z + (size_t)r0 * DD + col)       = p0;
            *reinterpret_cast<__half2*>(Z + (size_t)(r0 + 8) * DD + col) = p1;
        }
#undef AS
#undef BS
}

// ---------------- sparse aggregation (fp16 Z) + fused BN stats ----------------
// Index/dinv loads software-pipelined one batch ahead of the Z gathers.
__global__ __launch_bounds__(256) void agg_k(const __half* __restrict__ Z,
                                             float* __restrict__ Out, int layer) {
    __shared__ float sv[8][DD];
    int tid = threadIdx.x;
    int w = tid >> 5;
    int row = blockIdx.x * 8 + w;
    int lane = tid & 31;

    int deg = g_deg[row];
    const int* cols = &g_colidx[row * SLOT];
    float a[8];
    #pragma unroll
    for (int j = 0; j < 8; j++) a[j] = 0.f;

    int nfull = deg & ~3;        // batches of 4
    int cc[4];
    float dv[4];
    if (nfull > 0) {
        #pragma unroll
        for (int q = 0; q < 4; q++) {
            cc[q] = cols[q];
            dv[q] = rsqrtf((float)g_deg[cc[q]]);
        }
    }
    for (int p = 0; p < nfull; p += 4) {
        // issue gathers for current batch
        uint4 u[4];
        #pragma unroll
        for (int q = 0; q < 4; q++)
            u[q] = __ldg((const uint4*)(Z + (size_t)cc[q] * DD) + lane);
        // prefetch next batch's indices + dinv while gathers are in flight
        int ccn[4];
        float dvn[4];
        if (p + 8 <= nfull) {
            #pragma unroll
            for (int q = 0; q < 4; q++) {
                ccn[q] = cols[p + 4 + q];
                dvn[q] = rsqrtf((float)g_deg[ccn[q]]);
            }
        }
        // FMA chain on current batch
        #pragma unroll
        for (int q = 0; q < 4; q++) {
            float2 f0 = __half22float2(*reinterpret_cast<__half2*>(&u[q].x));
            float2 f1 = __half22float2(*reinterpret_cast<__half2*>(&u[q].y));
            float2 f2 = __half22float2(*reinterpret_cast<__half2*>(&u[q].z));
            float2 f3 = __half22float2(*reinterpret_cast<__half2*>(&u[q].w));
            a[0] = fmaf(dv[q], f0.x, a[0]); a[1] = fmaf(dv[q], f0.y, a[1]);
            a[2] = fmaf(dv[q], f1.x, a[2]); a[3] = fmaf(dv[q], f1.y, a[3]);
            a[4] = fmaf(dv[q], f2.x, a[4]); a[5] = fmaf(dv[q], f2.y, a[5]);
            a[6] = fmaf(dv[q], f3.x, a[6]); a[7] = fmaf(dv[q], f3.y, a[7]);
        }
        if (p + 8 <= nfull) {
            #pragma unroll
            for (int q = 0; q < 4; q++) { cc[q] = ccn[q]; dv[q] = dvn[q]; }
        }
    }
    for (int p = nfull; p < deg; p++) {
        int c = cols[p];
        float dvv = rsqrtf((float)g_deg[c]);
        uint4 u = __ldg((const uint4*)(Z + (size_t)c * DD) + lane);
        float2 f0 = __half22float2(*reinterpret_cast<__half2*>(&u.x));
        float2 f1 = __half22float2(*reinterpret_cast<__half2*>(&u.y));
        float2 f2 = __half22float2(*reinterpret_cast<__half2*>(&u.z));
        float2 f3 = __half22float2(*reinterpret_cast<__half2*>(&u.w));
        a[0] = fmaf(dvv, f0.x, a[0]); a[1] = fmaf(dvv, f0.y, a[1]);
        a[2] = fmaf(dvv, f1.x, a[2]); a[3] = fmaf(dvv, f1.y, a[3]);
        a[4] = fmaf(dvv, f2.x, a[4]); a[5] = fmaf(dvv, f2.y, a[5]);
        a[6] = fmaf(dvv, f3.x, a[6]); a[7] = fmaf(dvv, f3.y, a[7]);
    }
    float dr = rsqrtf((float)deg);
    #pragma unroll
    for (int j = 0; j < 8; j++) a[j] *= dr;

    float4* orow = reinterpret_cast<float4*>(Out + (size_t)row * DD);
    orow[lane * 2]     = make_float4(a[0], a[1], a[2], a[3]);
    orow[lane * 2 + 1] = make_float4(a[4], a[5], a[6], a[7]);

    #pragma unroll
    for (int j = 0; j < 8; j++) sv[w][lane * 8 + j] = a[j];
    __syncthreads();
    float s = 0.f, ss = 0.f;
    #pragma unroll
    for (int r = 0; r < 8; r++) {
        float v = sv[r][tid];
        s += v;
        ss = fmaf(v, v, ss);
    }
    atomicAdd(&g_stats[0][layer][tid], s);
    atomicAdd(&g_stats[1][layer][tid], ss);
}

// final BN apply (fp32 out, no relu)
__global__ __launch_bounds__(256) void apply_k(const float* __restrict__ A,
                                               float* __restrict__ out,
                                               const float* __restrict__ gamma,
                                               const float* __restrict__ beta) {
    __shared__ float ssc[DD], ssh[DD];
    int tid = threadIdx.x;
    {
        float mu = g_stats[0][2][tid] * (1.f / NN);
        float var = g_stats[1][2][tid] * (1.f / NN) - mu * mu;
        float rs = rsqrtf(var + BN_EPS);
        float sc = gamma[tid] * rs;
        ssc[tid] = sc;
        ssh[tid] = beta[tid] - mu * sc;
    }
    __syncthreads();
    int i = blockIdx.x * 256 + tid;
    int col = (i * 4) & (DD - 1);
    float4 v = reinterpret_cast<const float4*>(A)[i];
    float4 o;
    o.x = fmaf(v.x, ssc[col],     ssh[col]);
    o.y = fmaf(v.y, ssc[col + 1], ssh[col + 1]);
    o.z = fmaf(v.z, ssc[col + 2], ssh[col + 2]);
    o.w = fmaf(v.w, ssc[col + 3], ssh[col + 3]);
    reinterpret_cast<float4*>(out)[i] = o;
}

// ---------------- launch ----------------
extern "C" void kernel_launch(void* const* d_in, const int* in_sizes, int n_in,
                              void* d_out, int out_size) {
    const float* x   = (const float*)d_in[0];
    const void*  ei  = d_in[1];
    const float* W1  = (const float*)d_in[2];
    const float* b1  = (const float*)d_in[3];
    const float* W2  = (const float*)d_in[4];
    const float* b2  = (const float*)d_in[5];
    const float* W3  = (const float*)d_in[6];
    const float* b3  = (const float*)d_in[7];
    const float* g1  = (const float*)d_in[8];
    const float* be1 = (const float*)d_in[9];
    const float* g2  = (const float*)d_in[10];
    const float* be2 = (const float*)d_in[11];
    const float* g3  = (const float*)d_in[12];
    const float* be3 = (const float*)d_in[13];
    float* out = (float*)d_out;

    void *pZ, *pA, *pBm, *pDeg, *pSt, *pXh, *pWh, *pAh;
    cudaGetSymbolAddress(&pZ, g_Zh);
    cudaGetSymbolAddress(&pA, g_Abuf);
    cudaGetSymbolAddress(&pBm, g_bitmap);
    cudaGetSymbolAddress(&pDeg, g_deg);
    cudaGetSymbolAddress(&pSt, g_stats);
    cudaGetSymbolAddress(&pXh, g_Xh);
    cudaGetSymbolAddress(&pWh, g_Wh);
    cudaGetSymbolAddress(&pAh, g_Ah);
    __half* Zh = (__half*)pZ;
    float*  Ab = (float*)pA;
    __half* Xh = (__half*)pXh;
    __half* Wh = (__half*)pWh;
    __half* Ah = (__half*)pAh;

    const int GEMM_SMEM = NSTAGE * (BM * ASH + BNT * ASH) * 2;   // bytes
    cudaFuncSetAttribute(gemm_k, cudaFuncAttributeMaxDynamicSharedMemorySize, GEMM_SMEM);

    static cudaStream_t s_pre = nullptr;
    static cudaEvent_t ev_fork = nullptr, ev_join = nullptr;
    if (s_pre == nullptr) {
        cudaStreamCreateWithFlags(&s_pre, cudaStreamNonBlocking);
        cudaEventCreateWithFlags(&ev_fork, cudaEventDisableTiming);
        cudaEventCreateWithFlags(&ev_join, cudaEventDisableTiming);
    }

    // BN accumulators: one merged memset
    cudaMemsetAsync(pSt, 0, sizeof(float) * 2 * 3 * DD);

    // ---- fork: graph preprocessing (memsets + dedup), concurrent with
    //      convert + gemm1 on the main stream
    cudaEventRecord(ev_fork, 0);
    cudaStreamWaitEvent(s_pre, ev_fork, 0);
    cudaMemsetAsync(pBm, 0, sizeof(unsigned) * NN * (NN / 32), s_pre);
    cudaMemsetAsync(pDeg, 0, sizeof(int) * NN, s_pre);
    dedup_k<<<(UMAX + 255) / 256, 256, 0, s_pre>>>(ei);
    cudaEventRecord(ev_join, s_pre);

    // main: all fp32->fp16 conversions in ONE launch (x, W1, W2, W3)
    f2h4_k<<<(N4X + 3 * N4W + 255) / 256, 256>>>(
        (const float4*)x, (uint2*)Xh,
        (const float4*)W1, (const float4*)W2, (const float4*)W3,
        (uint2*)Wh);

    dim3 ggrid(NN / BM, DD / BNT);

    // layer 1 — concurrent with preprocessing fork
    gemm_k<<<ggrid, 256, GEMM_SMEM>>>(Xh, Wh + 0 * DD * DD, b1, Zh);
    cudaStreamWaitEvent(0, ev_join, 0);   // agg needs CSR + deg

    agg_k<<<NN / 8, 256>>>(Zh, Ab, 0);
    bnrelu_k<<<NN * DD / 8 / 256, 256>>>(Ab, Ah, 0, g1, be1);
    gemm_k<<<ggrid, 256, GEMM_SMEM>>>(Ah, Wh + 1 * DD * DD, b2, Zh);
    agg_k<<<NN / 8, 256>>>(Zh, Ab, 1);
    bnrelu_k<<<NN * DD / 8 / 256, 256>>>(Ab, Ah, 1, g2, be2);
    gemm_k<<<ggrid, 256, GEMM_SMEM>>>(Ah, Wh + 2 * DD * DD, b3, Zh);
    agg_k<<<NN / 8, 256>>>(Zh, Ab, 2);

    apply_k<<<NN * DD / 4 / 256, 256>>>(Ab, out, g3, be3);
}